// round 12
// baseline (speedup 1.0000x reference)
#include <cuda_runtime.h>
#include <cuda_bf16.h>
#include <cstdint>

// EngramMemory: rolling-hash n-gram gather — direct gather, 256-bit path (R11).
//
// tokens: (4, 4096) int32, tables: (8, 2048, 256) f32, out: (4, 4096, 2048) f32
// out[p][part*256 + d] = tables[part][h(part,p)][d]
//   h = fold over order-(2+oi) n-gram: h = (h*1000003 + tok + seed) & 2047,
//   seed = 1337 + 97*(2+oi) + 17*head, left zero-padded. All math fits in u32.
//
// R11: the memory path converged at ~26.5us across three configs with L1TEX
// ~63% as top pipe -> per-instruction LSU/L1TEX structural limit. Switch to
// 256-bit global accesses (ld/st .v8.b32, sm_100): 32B per thread per row,
// halving LDG/STG instruction count. evict_last is inline-legal on v8.b32
// (that's exactly what the R8 ptxas error demanded); stores evict_first.

namespace {
constexpr int B = 4;
constexpr int S = 4096;
constexpr int NUM_BUCKETS = 2048;
constexpr int HEAD_DIM = 256;
constexpr int PARTS = 8;                        // 2 orders * 4 heads
constexpr int ROWS = 8;                         // output rows per CTA
constexpr int ITER = ROWS / 2;                  // 2 rows processed per pass
constexpr unsigned PRIME = 1000003u;

struct F8 { unsigned r[8]; };

__device__ __forceinline__ F8 ldg256_evict_last(const void* p) {
    F8 v;
    asm volatile("ld.global.nc.L2::evict_last.v8.b32 "
                 "{%0,%1,%2,%3,%4,%5,%6,%7}, [%8];"
                 : "=r"(v.r[0]), "=r"(v.r[1]), "=r"(v.r[2]), "=r"(v.r[3]),
                   "=r"(v.r[4]), "=r"(v.r[5]), "=r"(v.r[6]), "=r"(v.r[7])
                 : "l"(p));
    return v;
}

__device__ __forceinline__ void stg256_evict_first(void* p, const F8& v) {
    asm volatile("st.global.L2::evict_first.v8.b32 [%0], "
                 "{%1,%2,%3,%4,%5,%6,%7,%8};"
                 :: "l"(p),
                    "r"(v.r[0]), "r"(v.r[1]), "r"(v.r[2]), "r"(v.r[3]),
                    "r"(v.r[4]), "r"(v.r[5]), "r"(v.r[6]), "r"(v.r[7])
                 : "memory");
}

__global__ __launch_bounds__(512, 3)
void engram_kernel(const int*   __restrict__ tokens,
                   const float* __restrict__ tables,
                   float*       __restrict__ out) {
    const int row0 = blockIdx.x * ROWS;     // base bs index
    const int tid  = threadIdx.x;

    __shared__ unsigned hidx[ROWS][PARTS];

    // ---- Hashes for all 8 rows (64 threads) -------------------------------
    if (tid < ROWS * PARTS) {
        const int r    = tid >> 3;
        const int part = tid & 7;
        const int bs   = row0 + r;
        const int b    = bs >> 12;          // / 4096
        const int s    = bs & (S - 1);      // % 4096
        const int oi    = part >> 2;        // 0 or 1
        const int head  = part & 3;
        const int order = 2 + oi;
        const unsigned seed = 1337u + 97u * (unsigned)order + 17u * (unsigned)head;
        unsigned h = 0u;
        #pragma unroll 3
        for (int i = 0; i < order; i++) {
            const int pos = s - order + 1 + i;
            unsigned tok = 0u;
            if (pos >= 0) tok = (unsigned)tokens[b * S + pos];
            h = (h * PRIME + tok + seed) & (NUM_BUCKETS - 1);
        }
        hidx[r][part] = h;
    }
    __syncthreads();

    // ---- Gather/scatter: 32B (float8) per thread per row ------------------
    // 256 threads cover one 2048-float row; 512 threads do 2 rows at once.
    const int half = tid >> 8;              // 0 or 1: which row of the pair
    const int c8   = tid & 255;             // float8 column within the row
    const int part = c8 >> 5;               // 32 float8 per 256-float head
    const int d8   = c8 & 31;

    const char* __restrict__ tbl =
        reinterpret_cast<const char*>(tables) +
        ((size_t)part * (NUM_BUCKETS * HEAD_DIM) + d8 * 8) * 4;
    char* __restrict__ dst =
        reinterpret_cast<char*>(out) +
        ((size_t)(row0 + half) * (PARTS * HEAD_DIM) + part * HEAD_DIM + d8 * 8) * 4;

    F8 v[ITER];
    #pragma unroll
    for (int j = 0; j < ITER; j++) {
        const unsigned h = hidx[2 * j + half][part];
        v[j] = ldg256_evict_last(tbl + (size_t)h * (HEAD_DIM * 4));
    }
    #pragma unroll
    for (int j = 0; j < ITER; j++) {
        stg256_evict_first(dst + (size_t)(2 * j) * (PARTS * HEAD_DIM * 4), v[j]);
    }
}
} // namespace

extern "C" void kernel_launch(void* const* d_in, const int* in_sizes, int n_in,
                              void* d_out, int out_size) {
    // Resolve input order by element count: tokens = 16384, tables = 4194304.
    int ti = 0, wi = 1;
    if (n_in >= 2 && in_sizes[0] > in_sizes[1]) { ti = 1; wi = 0; }
    const int*   tokens = (const int*)d_in[ti];
    const float* tables = (const float*)d_in[wi];
    float*       out    = (float*)d_out;

    engram_kernel<<<(B * S) / ROWS, 512>>>(tokens, tables, out);
}